// round 1
// baseline (speedup 1.0000x reference)
#include <cuda_runtime.h>
#include <math.h>

// Problem constants (from reference)
#define NPROB   4096        // B*S = 32*128
#define N_ACT   64
#define M_CON   32
#define SOFT    4
#define HARD    28          // M_CON - SOFT
#define ITERS   80
#define TPB     256

__device__ float g_xfeas[NPROB * N_ACT];   // scratch: anchor output

static constexpr float SIGMA_  = 1e-6f;
static constexpr float EPSLMO_ = 1e-4f;

// ---------------------------------------------------------------------------
// ADMM core in dual space.
//   M = P + sigma I + rho C^T C   (rho = 1)
//   Minv via Gauss-Jordan (in place in sM)
//   u0 = -Minv q ; cx0 = C u0 (per-owner reg) ; G = C Minv C^T (registers)
//   80 iters: v = z - y ; Cx = cx0 + G v ; z = clip(Cx + y, lo, hi) ; y += Cx - z
//   x_out = u0 + Minv (C^T v_last)
// Thread t < 2K owns constraint row t>>1, half t&1 (2*CHUNK = HALF cols of G).
// ---------------------------------------------------------------------------
template<int D, int K, int CHUNK>
__device__ __forceinline__ void admm_core(
    float* sC,    // K x DP   (DP = D+1)
    float* sM,    // D x DP   (M, then Minv)
    float* sTc,   // D x (CHUNK+1)  chunk of T = Minv C^T
    float* sq,    // D  (q; reused as x output)
    float* su0,   // D
    float* sv,    // 2K (double-buffered v)
    float* st,    // D  (temp C^T v)
    float* prow,  // D
    float* pcol,  // D
    float pdiag0, float pdiag1,   // P diagonal for i<64 / i>=64
    float lo, float hi)           // per-owner bounds (zeros for t >= 2K)
{
    constexpr int DP   = D + 1;
    constexpr int HALF = 2 * CHUNK;
    constexpr int TCW  = CHUNK + 1;
    const int t = threadIdx.x;

    // ---- M = P + sigma I + C^T C  (symmetric: lower triangle + mirror) ----
    constexpr int NTRI = D * (D + 1) / 2;
    for (int e = t; e < NTRI; e += TPB) {
        int i = (int)floorf((sqrtf(8.0f * (float)e + 1.0f) - 1.0f) * 0.5f);
        while ((i + 1) * (i + 2) / 2 <= e) ++i;
        while (i * (i + 1) / 2 > e) --i;
        int j = e - i * (i + 1) / 2;            // j <= i
        float acc = 0.f;
        for (int kk = 0; kk < K; ++kk)
            acc += sC[kk * DP + i] * sC[kk * DP + j];
        float val = acc;                         // rho = 1
        if (i == j) val += (i < 64 ? pdiag0 : pdiag1) + SIGMA_;
        sM[i * DP + j] = val;
        sM[j * DP + i] = val;
    }
    __syncthreads();

    // ---- Gauss-Jordan inverse in place (SPD, no pivoting) ----
    for (int kp = 0; kp < D; ++kp) {
        float pinv = 1.0f / sM[kp * DP + kp];
        if (t < D) {
            prow[t] = (t == kp) ? pinv : sM[kp * DP + t] * pinv;
            pcol[t] = sM[t * DP + kp];
        }
        __syncthreads();
        for (int e = t; e < D * D; e += TPB) {
            int i = e / D, j = e - i * D;
            float val;
            if (i == kp)      val = prow[j];
            else if (j == kp) val = -pcol[i] * pinv;
            else              val = sM[i * DP + j] - pcol[i] * prow[j];
            sM[i * DP + j] = val;
        }
        __syncthreads();
    }

    // ---- u0 = -Minv q ----
    if (t < D) {
        float acc = 0.f;
        for (int j = 0; j < D; ++j) acc += sM[t * DP + j] * sq[j];
        su0[t] = -acc;
    }
    __syncthreads();

    // ---- cx0 (per owner) ----
    const int row = (t < 2 * K) ? (t >> 1) : (K - 1);
    const int h   = t & 1;
    float cx0 = 0.f;
    if (t < 2 * K) {
        float acc = 0.f;
        for (int i = 0; i < D; ++i) acc += sC[row * DP + i] * su0[i];
        cx0 = acc;
    }

    // ---- G = C Minv C^T directly into registers, chunked over T columns ----
    float G[HALF];
#pragma unroll
    for (int c = 0; c < HALF; ++c) G[c] = 0.f;

#pragma unroll
    for (int ch = 0; ch < 4; ++ch) {
        const int base = ch * CHUNK;
        for (int e = t; e < D * CHUNK; e += TPB) {
            int i = e / CHUNK, cc = e - i * CHUNK;
            int b = base + cc;
            float acc = 0.f;
            for (int j = 0; j < D; ++j) acc += sM[i * DP + j] * sC[b * DP + j];
            sTc[i * TCW + cc] = acc;
        }
        __syncthreads();
        if (t < 2 * K && h == (ch >> 1)) {
            const int off = (ch & 1) * CHUNK;   // constant after unroll
            for (int i = 0; i < D; ++i) {
                float cai = sC[row * DP + i];
                const float* Trow = &sTc[i * TCW];
#pragma unroll
                for (int cc = 0; cc < CHUNK; ++cc)
                    G[off + cc] += cai * Trow[cc];
            }
        }
        __syncthreads();
    }

    // ---- 80 ADMM iterations in dual space ----
    float z = fminf(fmaxf(0.f, lo), hi);
    float y = 0.f;
    const int vbase = h * HALF;
    for (int it = 0; it < ITERS; ++it) {
        float* vb = sv + (it & 1) * K;
        if (t < 2 * K && h == 0) vb[row] = z - y;   // v = rho z - y, rho = 1
        __syncthreads();
        float a0 = 0.f, a1 = 0.f;
#pragma unroll
        for (int c = 0; c < HALF; c += 2) {
            a0 += G[c]     * vb[vbase + c];
            a1 += G[c + 1] * vb[vbase + c + 1];
        }
        float acc = a0 + a1;
        acc += __shfl_xor_sync(0xFFFFFFFFu, acc, 1);
        float Cx = cx0 + acc;
        float zn = fminf(fmaxf(Cx + y, lo), hi);
        y += Cx - zn;
        z = zn;
    }
    __syncthreads();

    // ---- recover x = u0 + Minv (C^T v_last) ----
    const float* vlast = sv + ((ITERS - 1) & 1) * K;
    if (t < D) {
        float acc = 0.f;
        for (int b = 0; b < K; ++b) acc += sC[b * DP + t] * vlast[b];
        st[t] = acc;
    }
    __syncthreads();
    if (t < D) {
        float acc = 0.f;
        for (int j = 0; j < D; ++j) acc += sM[t * DP + j] * st[j];
        sq[t] = su0[t] + acc;      // x written into sq
    }
    __syncthreads();
}

// ---------------------------------------------------------------------------
// Anchor QP: d = 68 (64 x + 4 slack), k = 100
// ---------------------------------------------------------------------------
#define A_D  68
#define A_K  100
#define A_DP 69
#define A_SMEM_FLOATS (A_K*A_DP + A_D*A_DP + A_D*26 + A_D*5 + 2*A_K)

__global__ void __launch_bounds__(TPB, 2)
anchor_kernel(const float* __restrict__ xr, const float* __restrict__ A,
              const float* __restrict__ b)
{
    extern __shared__ float smem[];
    float* sC   = smem;                       // 100*69
    float* sM   = sC   + A_K * A_DP;          // 68*69
    float* sTc  = sM   + A_D * A_DP;          // 68*26
    float* sq   = sTc  + A_D * 26;            // 68
    float* su0  = sq   + A_D;                 // 68
    float* sv   = su0  + A_D;                 // 200
    float* st   = sv   + 2 * A_K;             // 68
    float* prow = st   + A_D;                 // 68
    float* pcol = prow + A_D;                 // 68

    const int p = blockIdx.x;
    const int t = threadIdx.x;
    const float* Ap = A + (size_t)p * M_CON * N_ACT;
    const float* bp = b + (size_t)p * M_CON;
    const float* xp = xr + (size_t)p * N_ACT;

    if (t < A_D) sq[t] = (t < N_ACT) ? -xp[t] : 0.f;   // q = [-x_raw; 0]

    // C = [[I 0]; [Ah 0]; [As -Is]; [0 Is]]
    for (int e = t; e < A_K * A_D; e += TPB) {
        int r = e / A_D, i = e - r * A_D;
        float val = 0.f;
        if (r < 64) {
            val = (i == r) ? 1.f : 0.f;
        } else if (r < 92) {                   // hard rows
            if (i < 64) val = Ap[(r - 64) * N_ACT + i];
        } else if (r < 96) {                   // soft rows with -Is
            if (i < 64) val = Ap[(HARD + (r - 92)) * N_ACT + i];
            else        val = ((i - 64) == (r - 92)) ? -1.f : 0.f;
        } else {                               // [0 Is]
            val = (i >= 64 && (i - 64) == (r - 96)) ? 1.f : 0.f;
        }
        sC[r * A_DP + i] = val;
    }

    float lo = 0.f, hi = 0.f;
    if (t < 2 * A_K) {
        int row = t >> 1;
        if (row < 64)       { lo = 0.f;       hi = INFINITY; }
        else if (row < 92)  { lo = -INFINITY; hi = bp[row - 64]; }
        else if (row < 96)  { lo = -INFINITY; hi = bp[HARD + (row - 92)]; }
        else                { lo = 0.f;       hi = INFINITY; }
    }
    __syncthreads();

    admm_core<A_D, A_K, 25>(sC, sM, sTc, sq, su0, sv, st, prow, pcol,
                            1.0f, 2.0f /* 2*SLACK_P */, lo, hi);

    if (t < N_ACT) g_xfeas[(size_t)p * N_ACT + t] = sq[t];
}

// ---------------------------------------------------------------------------
// LMO QP: d = 64, k = 96.  Prologue fuses MLP gradient + row normalization.
// ---------------------------------------------------------------------------
#define L_D  64
#define L_K  96
#define L_DP 65
#define L_SMEM_FLOATS (L_K*L_DP + L_D*L_DP + L_D*25 + L_D*5 + 2*L_K + L_D + 256 + 32)

__global__ void __launch_bounds__(TPB, 2)
lmo_kernel(const float* __restrict__ A, const float* __restrict__ b,
           const float* __restrict__ W1, const float* __restrict__ w2,
           float* __restrict__ out)
{
    extern __shared__ float smem[];
    float* sC    = smem;                      // 96*65
    float* sM    = sC    + L_K * L_DP;        // 64*65
    float* sTc   = sM    + L_D * L_DP;        // 64*25
    float* sq    = sTc   + L_D * 25;          // 64
    float* su0   = sq    + L_D;               // 64
    float* sv    = su0   + L_D;               // 192
    float* st    = sv    + 2 * L_K;           // 64
    float* prow  = st    + L_D;               // 64
    float* pcol  = prow  + L_D;               // 64
    float* sx    = pcol  + L_D;               // 64  (x_feas)
    float* sh    = sx    + L_D;               // 256 ((1-h^2)*w2)
    float* srinv = sh    + 256;               // 32

    const int p = blockIdx.x;
    const int t = threadIdx.x;
    const float* Ap = A + (size_t)p * M_CON * N_ACT;
    const float* bp = b + (size_t)p * M_CON;

    if (t < N_ACT) sx[t] = g_xfeas[(size_t)p * N_ACT + t];
    __syncthreads();

    // h_j = tanh(x @ W1[:,j]) ; sh_j = (1-h^2)*w2_j      (j = t, all 256)
    {
        float acc = 0.f;
        for (int i = 0; i < N_ACT; ++i) acc += sx[i] * W1[i * 256 + t];
        float hh = tanhf(acc);
        sh[t] = (1.f - hh * hh) * w2[t];
    }
    // row inverse norms
    if (t < M_CON) {
        const float* Ar = Ap + t * N_ACT;
        float ss = 0.f;
        for (int i = 0; i < N_ACT; ++i) ss += Ar[i] * Ar[i];
        float nrm = fmaxf(sqrtf(ss), 1e-12f);
        srinv[t] = 1.0f / nrm;
    }
    __syncthreads();

    // g_i = sum_j sh_j * W1[i][j] ;  q = -g
    if (t < N_ACT) {
        const float* W1r = W1 + t * 256;
        float acc = 0.f;
        for (int j = 0; j < 256; ++j) acc += sh[j] * W1r[j];
        sq[t] = -acc;
    }

    // C = [I ; A_normalized]
    for (int e = t; e < L_K * L_D; e += TPB) {
        int r = e >> 6, i = e & 63;
        float val;
        if (r < 64) val = (i == r) ? 1.f : 0.f;
        else        val = Ap[(r - 64) * N_ACT + i] * srinv[r - 64];
        sC[r * L_DP + i] = val;
    }

    float lo = 0.f, hi = 0.f;
    if (t < 2 * L_K) {
        int row = t >> 1;
        if (row < 64) { lo = 0.f;       hi = INFINITY; }
        else          { lo = -INFINITY; hi = bp[row - 64] * srinv[row - 64]; }
    }
    __syncthreads();

    admm_core<L_D, L_K, 24>(sC, sM, sTc, sq, su0, sv, st, prow, pcol,
                            EPSLMO_, EPSLMO_, lo, hi);

    // x_fw = 0.9 * x_feas + 0.1 * c
    if (t < N_ACT) out[(size_t)p * N_ACT + t] = 0.9f * sx[t] + 0.1f * sq[t];
}

// ---------------------------------------------------------------------------
extern "C" void kernel_launch(void* const* d_in, const int* in_sizes, int n_in,
                              void* d_out, int out_size)
{
    const float* xr = (const float*)d_in[0];
    const float* A  = (const float*)d_in[1];
    const float* b  = (const float*)d_in[2];
    const float* W1 = (const float*)d_in[3];
    const float* w2 = (const float*)d_in[4];
    float* out = (float*)d_out;

    const int anchor_smem = A_SMEM_FLOATS * (int)sizeof(float);
    const int lmo_smem    = L_SMEM_FLOATS * (int)sizeof(float);
    cudaFuncSetAttribute(anchor_kernel, cudaFuncAttributeMaxDynamicSharedMemorySize, anchor_smem);
    cudaFuncSetAttribute(lmo_kernel,    cudaFuncAttributeMaxDynamicSharedMemorySize, lmo_smem);

    anchor_kernel<<<NPROB, TPB, anchor_smem>>>(xr, A, b);
    lmo_kernel<<<NPROB, TPB, lmo_smem>>>(A, b, W1, w2, out);
}

// round 2
// speedup vs baseline: 3.3754x; 3.3754x over previous
#include <cuda_runtime.h>
#include <math.h>

#define NPROB   4096
#define TPB     256
#define ITERS   80

__device__ float g_xfeas[NPROB * 64];

static constexpr float SIGMA_  = 1e-6f;
static constexpr float EPSLMO_ = 1e-4f;

#define AST 68   // shared A row stride (floats)

// ---------------------------------------------------------------------------
// Invert 32x32 SPD matrix (stride 36) by Gauss-Jordan + one Newton refinement.
// sH: input H (destroyed). sHi: output inverse. sT: 32x36 temp.
// ---------------------------------------------------------------------------
__device__ __forceinline__ void invert32(float* sH, float* sHi, float* sT,
                                         float* prow, float* pcol)
{
    const int t = threadIdx.x;
    for (int e = t; e < 32 * 36; e += TPB) sHi[e] = sH[e];
    __syncthreads();
    for (int k = 0; k < 32; ++k) {
        float pinv = 1.0f / sHi[k * 36 + k];
        if (t < 32) { prow[t] = (t == k) ? pinv : sHi[k * 36 + t] * pinv;
                      pcol[t] = sHi[t * 36 + k]; }
        __syncthreads();
        for (int e = t; e < 1024; e += TPB) {
            int i = e >> 5, j = e & 31;
            float val;
            if (i == k)      val = prow[j];
            else if (j == k) val = -pcol[i] * pinv;
            else             val = sHi[i * 36 + j] - pcol[i] * prow[j];
            sHi[i * 36 + j] = val;
        }
        __syncthreads();
    }
    // T = 2I - H * Hi
    for (int e = t; e < 1024; e += TPB) {
        int i = e >> 5, j = e & 31; float acc = 0.f;
        for (int m = 0; m < 32; ++m) acc += sH[i * 36 + m] * sHi[m * 36 + j];
        sT[i * 36 + j] = ((i == j) ? 2.0f : 0.0f) - acc;
    }
    __syncthreads();
    // H := Hi * T   (sH is dead, reuse as temp result)
    for (int e = t; e < 1024; e += TPB) {
        int i = e >> 5, j = e & 31; float acc = 0.f;
        for (int m = 0; m < 32; ++m) acc += sHi[i * 36 + m] * sT[m * 36 + j];
        sH[i * 36 + j] = acc;
    }
    __syncthreads();
    for (int e = t; e < 1024; e += TPB) {
        int i = e >> 5, j = e & 31; sHi[i * 36 + j] = sH[i * 36 + j];
    }
    __syncthreads();
}

// ---------------------------------------------------------------------------
// ANCHOR:  d = 68 (64 x + 4 slack), k = 100 (pad 104)
// M = diag(2+s, 3+s) + G^T G,  G = [A | S]  (32 x 68)
// ---------------------------------------------------------------------------
#define A_KP   104
#define A_HALF 52

__device__ __forceinline__ float qbaseA(int r, int c, const float* sA,
                                        const float* sP, float w0, float w1)
{
    if (r >= 100 || c >= 100) return 0.f;
    if (r < 64) {
        if (c < 64) return (r == c) ? w0 : 0.f;
        int cc = c - 64;
        return (cc < 32) ? w0 * sA[cc * AST + r] : 0.f;
    }
    if (c < 64) {
        int rr = r - 64;
        return (rr < 32) ? w0 * sA[rr * AST + c] : 0.f;
    }
    int rr = r - 64, cc = c - 64;
    if (rr < 32 && cc < 32) {
        float v = w0 * sP[rr * 36 + cc];
        if (rr >= 28 && rr == cc) v += w1;
        return v;
    }
    if (rr < 32) return (rr >= 28 && rr - 28 == cc - 32) ? -w1 : 0.f;
    if (cc < 32) return (cc >= 28 && cc - 28 == rr - 32) ? -w1 : 0.f;
    return (rr == cc) ? w1 : 0.f;
}

__global__ void __launch_bounds__(TPB, 2)
anchor_kernel(const float* __restrict__ xr, const float* __restrict__ Ain,
              const float* __restrict__ bin)
{
    constexpr float w0 = 1.0f / (2.0f + SIGMA_);
    constexpr float w1 = 1.0f / (3.0f + SIGMA_);
    extern __shared__ float sm[];
    float* sA   = sm;                    // 32*68
    float* sP   = sA   + 32 * AST;       // 32*36
    float* sH   = sP   + 32 * 36;
    float* sHi  = sH   + 32 * 36;
    float* sT   = sHi  + 32 * 36;
    float* sQR  = sT   + 32 * 36;        // 104*36
    float* sQRt = sQR  + A_KP * 36;      // 32*104
    float* sZ   = sQRt + 32 * A_KP;      // 104*36
    float* sv   = sZ   + A_KP * 36;      // 2*104
    float* vt1  = sv   + 2 * A_KP;       // 68
    float* vs   = vt1  + 68;             // 36
    float* vs2  = vs   + 36;             // 36
    float* vu0  = vs2  + 36;             // 68
    float* vtv  = vu0  + 68;             // 68
    float* prow = vtv  + 68;             // 36
    float* pcol = prow + 36;             // 36

    const int p = blockIdx.x;
    const int t = threadIdx.x;
    const float* Ap = Ain + (size_t)p * 32 * 64;
    const float* bp = bin + (size_t)p * 32;
    const float* xp = xr  + (size_t)p * 64;

    for (int e = t; e < 2048; e += TPB) {
        int r = e >> 6, i = e & 63;
        sA[r * AST + i] = Ap[e];
    }
    __syncthreads();

    // P = A A^T (32x32), float4 dots
    {
        const float4* A4 = (const float4*)sA;      // row r: r*17 float4
        for (int e = t; e < 1024; e += TPB) {
            int a = e >> 5, b = e & 31; float acc = 0.f;
            const float4* ra = A4 + a * 17; const float4* rb = A4 + b * 17;
#pragma unroll
            for (int k = 0; k < 16; ++k) {
                float4 x = ra[k], y = rb[k];
                acc += x.x * y.x + x.y * y.y + x.z * y.z + x.w * y.w;
            }
            sP[a * 36 + b] = acc;
        }
    }
    __syncthreads();
    // H = I + w0 P + w1*diag(soft rows)
    for (int e = t; e < 1024; e += TPB) {
        int a = e >> 5, b = e & 31;
        float v = w0 * sP[a * 36 + b];
        if (a == b) v += 1.0f + ((a >= 28) ? w1 : 0.0f);
        sH[a * 36 + b] = v;
    }
    __syncthreads();
    invert32(sH, sHi, sT, prow, pcol);

    // QR[r][j] = Q[r][64+j]   (K x 32, stride 36) and its transpose
    for (int e = t; e < A_KP * 32; e += TPB) {
        int r = e >> 5, j = e & 31;
        float v;
        if (r < 64) v = w0 * sA[j * AST + r];
        else if (r < 100) {
            int rr = r - 64;
            if (rr < 32) { v = w0 * sP[rr * 36 + j]; if (rr >= 28 && j == rr) v += w1; }
            else           v = (j == rr - 4) ? -w1 : 0.0f;
        } else v = 0.0f;
        sQR[r * 36 + j]  = v;
        sQRt[j * A_KP + r] = v;
    }
    __syncthreads();
    // Z = QR * Hinv   (K x 32)
    {
        const float4* Hi4 = (const float4*)sHi;    // row m: m*9 float4
        for (int e = t; e < A_KP * 8; e += TPB) {
            int r = e >> 3, j4 = e & 7;
            float4 acc = {0.f, 0.f, 0.f, 0.f};
            for (int m = 0; m < 32; ++m) {
                float q = sQR[r * 36 + m]; float4 hrow = Hi4[m * 9 + j4];
                acc.x += q * hrow.x; acc.y += q * hrow.y;
                acc.z += q * hrow.z; acc.w += q * hrow.w;
            }
            ((float4*)sZ)[r * 9 + j4] = acc;
        }
    }
    // u0 = -Minv q  via Woodbury ; q = [-x_raw; 0]
    if (t < 68) vt1[t] = (t < 64) ? (-w0 * xp[t]) : 0.0f;
    __syncthreads();
    if (t < 32) {
        float acc = 0.f;
        const float* Ar = sA + t * AST;
        for (int i = 0; i < 64; ++i) acc += Ar[i] * vt1[i];
        vs[t] = acc;
    }
    __syncthreads();
    if (t < 32) {
        float acc = 0.f;
        for (int m = 0; m < 32; ++m) acc += sHi[t * 36 + m] * vs[m];
        vs2[t] = acc;
    }
    __syncthreads();
    if (t < 68) {
        if (t < 64) {
            float acc = 0.f;
            for (int j = 0; j < 32; ++j) acc += sA[j * AST + t] * vs2[j];
            vu0[t] = -vt1[t] + w0 * acc;
        } else {
            vu0[t] = -w1 * vs2[28 + (t - 64)];
        }
    }
    __syncthreads();

    // bounds + cx0
    const int row = (t < 2 * A_KP) ? (t >> 1) : 0;
    const int h   = t & 1;
    float lo = 0.f, hi = 0.f, cx0 = 0.f;
    if (t < 2 * A_KP) {
        if (row < 64)      { lo = 0.f; hi = INFINITY; cx0 = vu0[row]; }
        else if (row < 92) {
            lo = -INFINITY; hi = bp[row - 64];
            float acc = 0.f; const float* Ar = sA + (row - 64) * AST;
            for (int i = 0; i < 64; ++i) acc += Ar[i] * vu0[i];
            cx0 = acc;
        } else if (row < 96) {
            lo = -INFINITY; hi = bp[28 + (row - 92)];
            float acc = 0.f; const float* Ar = sA + (row - 64) * AST;
            for (int i = 0; i < 64; ++i) acc += Ar[i] * vu0[i];
            cx0 = acc - vu0[64 + (row - 92)];
        } else if (row < 100) { lo = 0.f; hi = INFINITY; cx0 = vu0[64 + (row - 96)]; }
        else { lo = 0.f; hi = 0.f; cx0 = 0.f; }
    }

    // Ggram row (registers):  G[r][c] = Qbase(r,c) - Z[r] . QRt[:,c]
    float G[A_HALF];
#pragma unroll
    for (int c = 0; c < A_HALF; ++c) G[c] = 0.f;
    if (t < 2 * A_KP) {
        float Zr[32];
#pragma unroll
        for (int j = 0; j < 32; ++j) Zr[j] = sZ[row * 36 + j];
        const float4* Qt4 = (const float4*)sQRt;   // row j: j*26 float4
#pragma unroll
        for (int cc = 0; cc < 13; ++cc) {
            const int c0 = h * A_HALF + cc * 4;
            float4 acc;
            acc.x = qbaseA(row, c0 + 0, sA, sP, w0, w1);
            acc.y = qbaseA(row, c0 + 1, sA, sP, w0, w1);
            acc.z = qbaseA(row, c0 + 2, sA, sP, w0, w1);
            acc.w = qbaseA(row, c0 + 3, sA, sP, w0, w1);
            const int ci = c0 >> 2;
            for (int j = 0; j < 32; ++j) {
                float zj = Zr[j]; float4 u = Qt4[j * 26 + ci];
                acc.x -= zj * u.x; acc.y -= zj * u.y;
                acc.z -= zj * u.z; acc.w -= zj * u.w;
            }
            G[cc * 4 + 0] = acc.x; G[cc * 4 + 1] = acc.y;
            G[cc * 4 + 2] = acc.z; G[cc * 4 + 3] = acc.w;
        }
    }
    __syncthreads();

    // 80 ADMM iterations in dual space
    float z = fminf(fmaxf(0.f, lo), hi);
    float y = 0.f;
    for (int it = 0; it < ITERS; ++it) {
        float* vb = sv + (it & 1) * A_KP;
        if (t < 2 * A_KP && h == 0) vb[row] = z - y;
        __syncthreads();
        const float4* vb4 = (const float4*)vb + h * 13;
        float a0 = 0.f, a1 = 0.f, a2 = 0.f, a3 = 0.f;
#pragma unroll
        for (int cc = 0; cc < 13; ++cc) {
            float4 vv = vb4[cc];
            a0 += G[cc * 4 + 0] * vv.x; a1 += G[cc * 4 + 1] * vv.y;
            a2 += G[cc * 4 + 2] * vv.z; a3 += G[cc * 4 + 3] * vv.w;
        }
        float acc = (a0 + a1) + (a2 + a3);
        acc += __shfl_xor_sync(0xFFFFFFFFu, acc, 1);
        float Cx = cx0 + acc;
        float zn = fminf(fmaxf(Cx + y, lo), hi);
        y += Cx - zn; z = zn;
    }
    __syncthreads();

    // recover x = u0 + Minv(C^T v_last) via Woodbury
    const float* vlast = sv + ((ITERS - 1) & 1) * A_KP;
    if (t < 68) {
        if (t < 64) {
            float acc = vlast[t];
            for (int a = 0; a < 32; ++a) acc += sA[a * AST + t] * vlast[64 + a];
            vtv[t] = acc * w0;
        } else {
            int m = t - 64;
            vtv[t] = w1 * (-vlast[92 + m] + vlast[96 + m]);
        }
    }
    __syncthreads();
    if (t < 32) {
        float acc = 0.f;
        const float* Ar = sA + t * AST;
        for (int i = 0; i < 64; ++i) acc += Ar[i] * vtv[i];
        if (t >= 28) acc -= vtv[64 + (t - 28)];
        vs[t] = acc;
    }
    __syncthreads();
    if (t < 32) {
        float acc = 0.f;
        for (int m = 0; m < 32; ++m) acc += sHi[t * 36 + m] * vs[m];
        vs2[t] = acc;
    }
    __syncthreads();
    if (t < 64) {
        float acc = 0.f;
        for (int j = 0; j < 32; ++j) acc += sA[j * AST + t] * vs2[j];
        g_xfeas[(size_t)p * 64 + t] = vu0[t] + vtv[t] - w0 * acc;
    }
}

// ---------------------------------------------------------------------------
// LMO:  d = 64, k = 96.  M = (1+eps+sigma) I + At~ A~,  A~ normalized rows.
// ---------------------------------------------------------------------------
#define L_KP   96
#define L_HALF 48

__device__ __forceinline__ float qbaseL(int r, int c, const float* sA,
                                        const float* sP, float w)
{
    if (r < 64) {
        if (c < 64) return (r == c) ? w : 0.f;
        return w * sA[(c - 64) * AST + r];
    }
    if (c < 64) return w * sA[(r - 64) * AST + c];
    return w * sP[(r - 64) * 36 + (c - 64)];
}

__global__ void __launch_bounds__(TPB, 2)
lmo_kernel(const float* __restrict__ Ain, const float* __restrict__ bin,
           const float* __restrict__ W1, const float* __restrict__ w2,
           float* __restrict__ out)
{
    constexpr float w = 1.0f / (1.0f + EPSLMO_ + SIGMA_);
    extern __shared__ float sm[];
    float* sA    = sm;                    // 32*68 (normalized)
    float* sP    = sA    + 32 * AST;      // 32*36
    float* sH    = sP    + 32 * 36;
    float* sHi   = sH    + 32 * 36;
    float* sT    = sHi   + 32 * 36;
    float* sQR   = sT    + 32 * 36;       // 96*36
    float* sQRt  = sQR   + L_KP * 36;     // 32*96
    float* sZ    = sQRt  + 32 * L_KP;     // 96*36
    float* sv    = sZ    + L_KP * 36;     // 2*96
    float* vt1   = sv    + 2 * L_KP;      // 64
    float* vs    = vt1   + 64;            // 36
    float* vs2   = vs    + 36;            // 36
    float* vu0   = vs2   + 36;            // 64
    float* vtv   = vu0   + 64;            // 64
    float* prow  = vtv   + 64;            // 36
    float* pcol  = prow  + 36;            // 36
    float* sx    = pcol  + 36;            // 64
    float* shb   = sx    + 64;            // 256
    float* sg    = shb   + 256;           // 64
    float* srinv = sg    + 64;            // 32

    const int p = blockIdx.x;
    const int t = threadIdx.x;
    const float* Ap = Ain + (size_t)p * 32 * 64;
    const float* bp = bin + (size_t)p * 32;

    // load raw A, x_feas
    for (int e = t; e < 2048; e += TPB) {
        int r = e >> 6, i = e & 63;
        sA[r * AST + i] = Ap[e];
    }
    if (t < 64) sx[t] = g_xfeas[(size_t)p * 64 + t];
    __syncthreads();

    // row inverse norms, then normalize A in place
    if (t < 32) {
        const float* Ar = sA + t * AST;
        float ss = 0.f;
        for (int i = 0; i < 64; ++i) ss += Ar[i] * Ar[i];
        srinv[t] = 1.0f / fmaxf(sqrtf(ss), 1e-12f);
    }
    // MLP h-pass (coalesced over hidden dim)
    {
        float acc = 0.f;
        for (int i = 0; i < 64; ++i) acc += sx[i] * W1[i * 256 + t];
        float hh = tanhf(acc);
        shb[t] = (1.f - hh * hh) * w2[t];
    }
    __syncthreads();
    for (int e = t; e < 2048; e += TPB) {
        int r = e >> 6, i = e & 63;
        sA[r * AST + i] *= srinv[r];
    }
    // MLP g-pass: warp per 8 output rows, coalesced W1 reads
    {
        int wid = t >> 5, lane = t & 31;
        for (int rr = 0; rr < 8; ++rr) {
            int i = wid * 8 + rr;
            const float* Wr = W1 + i * 256;
            float acc = 0.f;
#pragma unroll
            for (int k = 0; k < 8; ++k) acc += Wr[k * 32 + lane] * shb[k * 32 + lane];
#pragma unroll
            for (int o = 16; o; o >>= 1) acc += __shfl_xor_sync(0xFFFFFFFFu, acc, o);
            if (lane == 0) sg[i] = acc;
        }
    }
    __syncthreads();

    // P = A~ A~^T
    {
        const float4* A4 = (const float4*)sA;
        for (int e = t; e < 1024; e += TPB) {
            int a = e >> 5, b = e & 31; float acc = 0.f;
            const float4* ra = A4 + a * 17; const float4* rb = A4 + b * 17;
#pragma unroll
            for (int k = 0; k < 16; ++k) {
                float4 x = ra[k], y = rb[k];
                acc += x.x * y.x + x.y * y.y + x.z * y.z + x.w * y.w;
            }
            sP[a * 36 + b] = acc;
        }
    }
    __syncthreads();
    for (int e = t; e < 1024; e += TPB) {
        int a = e >> 5, b = e & 31;
        float v = w * sP[a * 36 + b];
        if (a == b) v += 1.0f;
        sH[a * 36 + b] = v;
    }
    __syncthreads();
    invert32(sH, sHi, sT, prow, pcol);

    for (int e = t; e < L_KP * 32; e += TPB) {
        int r = e >> 5, j = e & 31;
        float v = (r < 64) ? (w * sA[j * AST + r]) : (w * sP[(r - 64) * 36 + j]);
        sQR[r * 36 + j]  = v;
        sQRt[j * L_KP + r] = v;
    }
    __syncthreads();
    {
        const float4* Hi4 = (const float4*)sHi;
        for (int e = t; e < L_KP * 8; e += TPB) {
            int r = e >> 3, j4 = e & 7;
            float4 acc = {0.f, 0.f, 0.f, 0.f};
            for (int m = 0; m < 32; ++m) {
                float q = sQR[r * 36 + m]; float4 hrow = Hi4[m * 9 + j4];
                acc.x += q * hrow.x; acc.y += q * hrow.y;
                acc.z += q * hrow.z; acc.w += q * hrow.w;
            }
            ((float4*)sZ)[r * 9 + j4] = acc;
        }
    }
    // u0 = -Minv q, q = -g  =>  t1 = -w g
    if (t < 64) vt1[t] = -w * sg[t];
    __syncthreads();
    if (t < 32) {
        float acc = 0.f;
        const float* Ar = sA + t * AST;
        for (int i = 0; i < 64; ++i) acc += Ar[i] * vt1[i];
        vs[t] = acc;
    }
    __syncthreads();
    if (t < 32) {
        float acc = 0.f;
        for (int m = 0; m < 32; ++m) acc += sHi[t * 36 + m] * vs[m];
        vs2[t] = acc;
    }
    __syncthreads();
    if (t < 64) {
        float acc = 0.f;
        for (int j = 0; j < 32; ++j) acc += sA[j * AST + t] * vs2[j];
        vu0[t] = -vt1[t] + w * acc;
    }
    __syncthreads();

    const int row = (t < 2 * L_KP) ? (t >> 1) : 0;
    const int h   = t & 1;
    float lo = 0.f, hi = 0.f, cx0 = 0.f;
    if (t < 2 * L_KP) {
        if (row < 64) { lo = 0.f; hi = INFINITY; cx0 = vu0[row]; }
        else {
            int a = row - 64;
            lo = -INFINITY; hi = bp[a] * srinv[a];
            float acc = 0.f; const float* Ar = sA + a * AST;
            for (int i = 0; i < 64; ++i) acc += Ar[i] * vu0[i];
            cx0 = acc;
        }
    }

    float G[L_HALF];
#pragma unroll
    for (int c = 0; c < L_HALF; ++c) G[c] = 0.f;
    if (t < 2 * L_KP) {
        float Zr[32];
#pragma unroll
        for (int j = 0; j < 32; ++j) Zr[j] = sZ[row * 36 + j];
        const float4* Qt4 = (const float4*)sQRt;   // row j: j*24 float4
#pragma unroll
        for (int cc = 0; cc < 12; ++cc) {
            const int c0 = h * L_HALF + cc * 4;
            float4 acc;
            acc.x = qbaseL(row, c0 + 0, sA, sP, w);
            acc.y = qbaseL(row, c0 + 1, sA, sP, w);
            acc.z = qbaseL(row, c0 + 2, sA, sP, w);
            acc.w = qbaseL(row, c0 + 3, sA, sP, w);
            const int ci = c0 >> 2;
            for (int j = 0; j < 32; ++j) {
                float zj = Zr[j]; float4 u = Qt4[j * 24 + ci];
                acc.x -= zj * u.x; acc.y -= zj * u.y;
                acc.z -= zj * u.z; acc.w -= zj * u.w;
            }
            G[cc * 4 + 0] = acc.x; G[cc * 4 + 1] = acc.y;
            G[cc * 4 + 2] = acc.z; G[cc * 4 + 3] = acc.w;
        }
    }
    __syncthreads();

    float z = fminf(fmaxf(0.f, lo), hi);
    float y = 0.f;
    for (int it = 0; it < ITERS; ++it) {
        float* vb = sv + (it & 1) * L_KP;
        if (t < 2 * L_KP && h == 0) vb[row] = z - y;
        __syncthreads();
        const float4* vb4 = (const float4*)vb + h * 12;
        float a0 = 0.f, a1 = 0.f, a2 = 0.f, a3 = 0.f;
#pragma unroll
        for (int cc = 0; cc < 12; ++cc) {
            float4 vv = vb4[cc];
            a0 += G[cc * 4 + 0] * vv.x; a1 += G[cc * 4 + 1] * vv.y;
            a2 += G[cc * 4 + 2] * vv.z; a3 += G[cc * 4 + 3] * vv.w;
        }
        float acc = (a0 + a1) + (a2 + a3);
        acc += __shfl_xor_sync(0xFFFFFFFFu, acc, 1);
        float Cx = cx0 + acc;
        float zn = fminf(fmaxf(Cx + y, lo), hi);
        y += Cx - zn; z = zn;
    }
    __syncthreads();

    const float* vlast = sv + ((ITERS - 1) & 1) * L_KP;
    if (t < 64) {
        float acc = vlast[t];
        for (int a = 0; a < 32; ++a) acc += sA[a * AST + t] * vlast[64 + a];
        vtv[t] = acc * w;
    }
    __syncthreads();
    if (t < 32) {
        float acc = 0.f;
        const float* Ar = sA + t * AST;
        for (int i = 0; i < 64; ++i) acc += Ar[i] * vtv[i];
        vs[t] = acc;
    }
    __syncthreads();
    if (t < 32) {
        float acc = 0.f;
        for (int m = 0; m < 32; ++m) acc += sHi[t * 36 + m] * vs[m];
        vs2[t] = acc;
    }
    __syncthreads();
    if (t < 64) {
        float acc = 0.f;
        for (int j = 0; j < 32; ++j) acc += sA[j * AST + t] * vs2[j];
        float c_sol = vu0[t] + vtv[t] - w * acc;
        out[(size_t)p * 64 + t] = 0.9f * sx[t] + 0.1f * c_sol;
    }
}

// ---------------------------------------------------------------------------
extern "C" void kernel_launch(void* const* d_in, const int* in_sizes, int n_in,
                              void* d_out, int out_size)
{
    const float* xr = (const float*)d_in[0];
    const float* A  = (const float*)d_in[1];
    const float* b  = (const float*)d_in[2];
    const float* W1 = (const float*)d_in[3];
    const float* w2 = (const float*)d_in[4];
    float* out = (float*)d_out;

    const int a_smem = (32*AST + 4*32*36 + A_KP*36 + 32*A_KP + A_KP*36 + 2*A_KP
                        + 68 + 36 + 36 + 68 + 68 + 36 + 36 + 16) * (int)sizeof(float);
    const int l_smem = (32*AST + 4*32*36 + L_KP*36 + 32*L_KP + L_KP*36 + 2*L_KP
                        + 64 + 36 + 36 + 64 + 64 + 36 + 36 + 64 + 256 + 64 + 32 + 16) * (int)sizeof(float);

    cudaFuncSetAttribute(anchor_kernel, cudaFuncAttributeMaxDynamicSharedMemorySize, a_smem);
    cudaFuncSetAttribute(lmo_kernel,    cudaFuncAttributeMaxDynamicSharedMemorySize, l_smem);

    anchor_kernel<<<NPROB, TPB, a_smem>>>(xr, A, b);
    lmo_kernel<<<NPROB, TPB, l_smem>>>(A, b, W1, w2, out);
}